// round 16
// baseline (speedup 1.0000x reference)
#include <cuda_runtime.h>
#include <cuda_bf16.h>
#include <cstdint>

// Problem constants
constexpr int B = 16;
constexpr int T = 2048;
constexpr int D = 256;
constexpr int MBIG = B * T;          // 32768
constexpr int SCAN_L = 32;
constexpr int SCAN_P = T / SCAN_L;   // 64
constexpr float GAMMA   = 0.9f;
constexpr float GAMMA32 = 0.03433683820292512f;  // 0.9^32

// ---------------------------------------------------------------------------
// Static device scratch
// ---------------------------------------------------------------------------
__device__ __align__(16) __nv_bfloat16 g_yhi[T * D];
__device__ __align__(16) __nv_bfloat16 g_ylo[T * D];
__device__ __align__(16) __nv_bfloat16 g_wqt_hi[D * D];  // transposed: [n][k]
__device__ __align__(16) __nv_bfloat16 g_wqt_lo[D * D];
__device__ __align__(16) __nv_bfloat16 g_wkt_hi[D * D];
__device__ __align__(16) __nv_bfloat16 g_wkt_lo[D * D];
__device__ float g_wvsum[D];
__device__ float g_c[T * D];
__device__ float g_S[T * D];
__device__ float g_carry[SCAN_P * D];
__device__ float g_pre[SCAN_P * D];

// ---------------------------------------------------------------------------
// Helpers (baseline PTX only)
// ---------------------------------------------------------------------------
__device__ __forceinline__ uint32_t smem_u32(const void* p) {
    uint32_t a;
    asm("{ .reg .u64 t; cvta.to.shared.u64 t, %1; cvt.u32.u64 %0, t; }"
        : "=r"(a) : "l"(p));
    return a;
}

__device__ __forceinline__ void cp16(uint32_t s, const void* g) {
    asm volatile("cp.async.cg.shared.global [%0], [%1], 16;"
                 :: "r"(s), "l"(g) : "memory");
}
__device__ __forceinline__ void cp_commit() {
    asm volatile("cp.async.commit_group;" ::: "memory");
}
template <int N>
__device__ __forceinline__ void cp_wait() {
    asm volatile("cp.async.wait_group %0;" :: "n"(N) : "memory");
}

#define LDSM_X4(r0, r1, r2, r3, addr) \
    asm volatile("ldmatrix.sync.aligned.m8n8.x4.shared.b16 {%0,%1,%2,%3}, [%4];" \
                 : "=r"(r0), "=r"(r1), "=r"(r2), "=r"(r3) : "r"(addr))

#define MMA_BF16(c, a, b) \
    asm volatile("mma.sync.aligned.m16n8k16.row.col.f32.bf16.bf16.f32 " \
                 "{%0,%1,%2,%3}, {%4,%5,%6,%7}, {%8,%9}, {%0,%1,%2,%3};" \
                 : "+f"((c)[0]), "+f"((c)[1]), "+f"((c)[2]), "+f"((c)[3]) \
                 : "r"((a)[0]), "r"((a)[1]), "r"((a)[2]), "r"((a)[3]), \
                   "r"((b)[0]), "r"((b)[1]))

// ---------------------------------------------------------------------------
// Kernel W: split+transpose Wq/Wk into bf16 hi/lo [n][k]  (grid.x 0,1)
//           + wv_sum row-sums                              (grid.x 2)
// ---------------------------------------------------------------------------
__global__ void prep_kernel(const float* __restrict__ Wq,
                            const float* __restrict__ Wk,
                            const float* __restrict__ Wv) {
    if (blockIdx.x == 2) {
        // wv_sum for rows [blockIdx.y*32, +32)
        const int warp = threadIdx.x >> 5, lane = threadIdx.x & 31;
        const int row = blockIdx.y * 32 + warp * 4 + (lane >> 3);
        // 8 warps x 4 rows covers 32 rows; use 4 lanes-groups of 8 per row
        // simpler: each warp does 4 rows serially
        const int r0 = blockIdx.y * 32 + warp * 4;
#pragma unroll
        for (int rr = 0; rr < 4; ++rr) {
            const int r = r0 + rr;
            float s = 0.f;
#pragma unroll
            for (int i = 0; i < 8; ++i)
                s += Wv[r * D + lane + 32 * i];
#pragma unroll
            for (int o = 16; o > 0; o >>= 1)
                s += __shfl_xor_sync(0xffffffffu, s, o);
            if (lane == 0) g_wvsum[r] = s;
        }
        (void)row;
        return;
    }
    const float* W = blockIdx.x ? Wk : Wq;
    __nv_bfloat16* hi = blockIdx.x ? g_wkt_hi : g_wqt_hi;
    __nv_bfloat16* lo = blockIdx.x ? g_wkt_lo : g_wqt_lo;
    const int n  = blockIdx.y * 32 + (threadIdx.x & 31);
    const int k0 = (threadIdx.x >> 5) * 32;
#pragma unroll 4
    for (int kk = 0; kk < 32; ++kk) {
        const int k = k0 + kk;
        float v = W[k * D + n];
        __nv_bfloat16 h = __float2bfloat16_rn(v);
        hi[n * D + k] = h;
        lo[n * D + k] = __float2bfloat16_rn(v - __bfloat162float(h));
    }
}

// ---------------------------------------------------------------------------
// Kernel B: per-t fold over batch (y hi/lo split only).
// ---------------------------------------------------------------------------
__global__ void y_kernel(const float* __restrict__ x) {
    const int t = blockIdx.x;
    const int d = threadIdx.x;
    __shared__ float xs[B][D];
    __shared__ float wvs[D];
    __shared__ float vs[B];

    wvs[d] = g_wvsum[d];
#pragma unroll
    for (int b = 0; b < B; ++b)
        xs[b][d] = x[((size_t)b * T + t) * D + d];
    __syncthreads();

    const int warp = d >> 5, lane = d & 31;
#pragma unroll
    for (int bb = 0; bb < 2; ++bb) {
        const int b = warp * 2 + bb;
        float p = 0.f;
#pragma unroll
        for (int i = 0; i < D / 32; ++i)
            p += xs[b][lane + 32 * i] * wvs[lane + 32 * i];
#pragma unroll
        for (int o = 16; o > 0; o >>= 1)
            p += __shfl_xor_sync(0xffffffffu, p, o);
        if (lane == 0) vs[b] = p;
    }
    __syncthreads();

    float acc = 0.f;
#pragma unroll
    for (int b = 0; b < B; ++b)
        acc += vs[b] * xs[b][d];
    __nv_bfloat16 h = __float2bfloat16_rn(acc);
    g_yhi[t * D + d] = h;
    g_ylo[t * D + d] = __float2bfloat16_rn(acc - __bfloat162float(h));
}

// ---------------------------------------------------------------------------
// Blocked decay scan
// ---------------------------------------------------------------------------
__global__ __launch_bounds__(256) void scan_local_kernel() {
    const int p = blockIdx.x, d = threadIdx.x;
    float v[SCAN_L];
#pragma unroll
    for (int i = 0; i < SCAN_L; ++i) {
        const int t = p * SCAN_L + i;
        v[i] = (t == 0) ? 0.f : g_c[t * D + d];
    }
    float r = 0.f;
#pragma unroll
    for (int i = 0; i < SCAN_L; ++i) {
        r = GAMMA * r + v[i];
        v[i] = r;
    }
#pragma unroll
    for (int i = 0; i < SCAN_L; ++i)
        g_S[(p * SCAN_L + i) * D + d] = v[i];
    g_carry[p * D + d] = r;
}

__global__ __launch_bounds__(256) void scan_carry_kernel() {
    const int d = threadIdx.x;
    float c[SCAN_P];
#pragma unroll
    for (int p = 0; p < SCAN_P; ++p)
        c[p] = g_carry[p * D + d];
    float r = 0.f;
#pragma unroll
    for (int p = 0; p < SCAN_P; ++p) {
        g_pre[p * D + d] = r;
        r = c[p] + GAMMA32 * r;
    }
}

__global__ __launch_bounds__(256) void scan_combine_kernel() {
    const int p = blockIdx.x, d = threadIdx.x;
    const float pre = g_pre[p * D + d];
    float v[SCAN_L];
#pragma unroll
    for (int i = 0; i < SCAN_L; ++i)
        v[i] = g_S[(p * SCAN_L + i) * D + d];
    float gp = GAMMA;
#pragma unroll
    for (int i = 0; i < SCAN_L; ++i) {
        v[i] += gp * pre;
        gp *= GAMMA;
    }
#pragma unroll
    for (int i = 0; i < SCAN_L; ++i)
        g_S[(p * SCAN_L + i) * D + d] = v[i];
    if (p == 0)
        g_S[d] = v[1];   // S[0] := r[1]
}

// ---------------------------------------------------------------------------
// Small GEMM: c = y @ Wk^T  (64x64 tiles, split inputs pre-materialized)
// ---------------------------------------------------------------------------
constexpr int SMEM_SMALL = 3 * 2 * (64 * 64 + 64 * 64);    // 49152

__global__ __launch_bounds__(256, 3)
void yk_gemm() {
    constexpr int MT = 2, NT = 2;
    constexpr int BM = 64, BN = 64;
    constexpr int ASZ = BM * 64;
    constexpr int BSZ = BN * 64;
    constexpr int STAGE = 2 * (ASZ + BSZ);

    extern __shared__ char smem[];
    const uint32_t smem_u = smem_u32(smem);

    const int tid  = threadIdx.x;
    const int wid  = tid >> 5;
    const int lane = tid & 31;
    const int wm = (wid >> 2) * (MT * 16);
    const int wn = (wid & 3) * (NT * 8);

    const int bm = blockIdx.x * BM;
    const int bn = blockIdx.y * BN;

    const __nv_bfloat16* const Ahi = g_yhi + (size_t)bm * D;
    const __nv_bfloat16* const Alo = g_ylo + (size_t)bm * D;
    const __nv_bfloat16* const Bhi = g_wkt_hi + (size_t)bn * D;
    const __nv_bfloat16* const Blo = g_wkt_lo + (size_t)bn * D;

    auto load_stage = [&](int stg, int chunk) {
        const int kc = chunk * 32;
        const uint32_t sb = smem_u + stg * STAGE;
        const __nv_bfloat16* srcs[4] = { Ahi, Alo, Bhi, Blo };
#pragma unroll
        for (int t4 = 0; t4 < 4; ++t4) {
            const uint32_t tb = sb + t4 * ASZ;
            const int r = tid >> 2, ch = tid & 3;
            const uint32_t s = tb + r * 64 + ((ch ^ ((r >> 1) & 3)) << 4);
            cp16(s, srcs[t4] + (size_t)r * D + kc + ch * 8);
        }
    };

    const int laneA_r = ((lane & 8) ? 8 : 0) + (lane & 7);
    const int laneA_k = (lane & 16) ? 1 : 0;
    const int mi = lane >> 3;
    const int laneB_ns = mi >> 1;
    const int laneB_k  = mi & 1;
    const int laneB_r  = lane & 7;

    float acc[MT][NT][4];
#pragma unroll
    for (int a = 0; a < MT; ++a)
#pragma unroll
        for (int b = 0; b < NT; ++b)
#pragma unroll
            for (int q = 0; q < 4; ++q) acc[a][b][q] = 0.f;

    load_stage(0, 0);
    cp_commit();
    load_stage(1, 1);
    cp_commit();

#pragma unroll 1
    for (int chunk = 0; chunk < 8; ++chunk) {
        const int stg = chunk % 3;
        if (chunk + 2 < 8) {
            load_stage((chunk + 2) % 3, chunk + 2);
            cp_commit();
            cp_wait<2>();
        } else if (chunk + 1 < 8) {
            cp_wait<1>();
        } else {
            cp_wait<0>();
        }
        __syncthreads();

        const uint32_t sb = smem_u + stg * STAGE;
#pragma unroll
        for (int ks = 0; ks < 32; ks += 16) {
            const int ko = (ks >> 3);
            uint32_t aH[MT][4], aL[MT][4], bH[NT][2], bL[NT][2];
#pragma unroll
            for (int mt = 0; mt < MT; ++mt) {
                const int R = wm + mt * 16 + laneA_r;
                const int kk = ko + laneA_k;
                const uint32_t sw = R * 64 + ((kk ^ ((R >> 1) & 3)) << 4);
                LDSM_X4(aH[mt][0], aH[mt][1], aH[mt][2], aH[mt][3], sb + sw);
                LDSM_X4(aL[mt][0], aL[mt][1], aL[mt][2], aL[mt][3],
                        sb + ASZ + sw);
            }
#pragma unroll
            for (int g = 0; g < NT / 2; ++g) {
                const int R = wn + (2 * g + laneB_ns) * 8 + laneB_r;
                const int kk = ko + laneB_k;
                const uint32_t sw = R * 64 + ((kk ^ ((R >> 1) & 3)) << 4);
                LDSM_X4(bH[2 * g][0], bH[2 * g][1],
                        bH[2 * g + 1][0], bH[2 * g + 1][1], sb + 2 * ASZ + sw);
                LDSM_X4(bL[2 * g][0], bL[2 * g][1],
                        bL[2 * g + 1][0], bL[2 * g + 1][1],
                        sb + 2 * ASZ + BSZ + sw);
            }
#pragma unroll
            for (int mt = 0; mt < MT; ++mt)
#pragma unroll
                for (int nt = 0; nt < NT; ++nt)
                    MMA_BF16(acc[mt][nt], aH[mt], bH[nt]);
#pragma unroll
            for (int mt = 0; mt < MT; ++mt)
#pragma unroll
                for (int nt = 0; nt < NT; ++nt)
                    MMA_BF16(acc[mt][nt], aL[mt], bH[nt]);
#pragma unroll
            for (int mt = 0; mt < MT; ++mt)
#pragma unroll
                for (int nt = 0; nt < NT; ++nt)
                    MMA_BF16(acc[mt][nt], aH[mt], bL[nt]);
        }
        __syncthreads();
    }

    const int rbase = bm + wm + (lane >> 2);
    const int cbase = bn + wn + 2 * (lane & 3);
#pragma unroll
    for (int mt = 0; mt < MT; ++mt) {
        const int R0 = rbase + mt * 16;
#pragma unroll
        for (int nt = 0; nt < NT; ++nt) {
            const int C = cbase + nt * 8;
            float2 v01, v23;
            v01.x = acc[mt][nt][0];
            v01.y = acc[mt][nt][1];
            v23.x = acc[mt][nt][2];
            v23.y = acc[mt][nt][3];
            *reinterpret_cast<float2*>(&g_c[(size_t)R0 * D + C]) = v01;
            *reinterpret_cast<float2*>(&g_c[(size_t)(R0 + 8) * D + C]) = v23;
        }
    }
}

// ---------------------------------------------------------------------------
// Big GEMM, fused x-split: out[m, 0:256] = S2 .* (x @ Wq)
// 512 threads (16 warps = 4/SMSP), BM=128, full N=256, x read once as fp32.
// Warp grid 4(M) x 4(N): warp tile 32 x 64. 2-stage pipeline, 128KB SMEM.
// Stage: Af32 16K | Ahi 8K | Alo 8K | Bhi 16K | Blo 16K = 64K.
// ---------------------------------------------------------------------------
constexpr int XQ_STAGE = 65536;
constexpr int SMEM_BIG = 2 * XQ_STAGE;   // 131072

__global__ __launch_bounds__(512, 1)
void xq_gemm(const float* __restrict__ x, float* __restrict__ out) {
    constexpr int AF32 = 0;         // 128 rows x 128B
    constexpr int AHI  = 16384;     // 128 rows x 64B, swizzled
    constexpr int ALO  = 24576;
    constexpr int BHI  = 32768;     // 256 rows x 64B, swizzled
    constexpr int BLO  = 49152;

    extern __shared__ char smem[];
    const uint32_t smem_u = smem_u32(smem);

    const int tid  = threadIdx.x;
    const int wid  = tid >> 5;
    const int lane = tid & 31;
    const int wm = (wid >> 2) * 32;     // 4 M groups of 32 rows
    const int wn = (wid & 3) * 64;      // 4 N groups of 64 cols

    const int bm = blockIdx.x * 128;
    const float* const Asrc = x + (size_t)bm * D;

    auto load_stage = [&](int stg, int chunk) {
        const int kc = chunk * 32;
        const uint32_t sb = smem_u + stg * XQ_STAGE;
        // A fp32: 128 rows x 8 chunks(16B) = 1024 cp16 over 512 threads
#pragma unroll
        for (int i = 0; i < 2; ++i) {
            const int q = tid + i * 512;
            const int r = q >> 3, ch = q & 7;
            cp16(sb + AF32 + r * 128 + ch * 16,
                 Asrc + (size_t)r * D + kc + ch * 4);
        }
        // B hi / B lo: 256 rows x 4 chunks each
#pragma unroll
        for (int i = 0; i < 2; ++i) {
            const int q = tid + i * 512;
            const int r = q >> 2, ch = q & 3;
            const uint32_t sw = r * 64 + ((ch ^ ((r >> 1) & 3)) << 4);
            cp16(sb + BHI + sw, g_wqt_hi + (size_t)r * D + kc + ch * 8);
            cp16(sb + BLO + sw, g_wqt_lo + (size_t)r * D + kc + ch * 8);
        }
    };

    const int laneA_r = ((lane & 8) ? 8 : 0) + (lane & 7);
    const int laneA_k = (lane & 16) ? 1 : 0;
    const int mi = lane >> 3;
    const int laneB_ns = mi >> 1;
    const int laneB_k  = mi & 1;
    const int laneB_r  = lane & 7;

    float acc[2][8][4];   // [mt][nt][4]
#pragma unroll
    for (int a = 0; a < 2; ++a)
#pragma unroll
        for (int b = 0; b < 8; ++b)
#pragma unroll
            for (int q = 0; q < 4; ++q) acc[a][b][q] = 0.f;

    load_stage(0, 0);
    cp_commit();

#pragma unroll 1
    for (int chunk = 0; chunk < 8; ++chunk) {
        const int stg = chunk & 1;
        if (chunk < 7) {
            load_stage(stg ^ 1, chunk + 1);
            cp_commit();
            cp_wait<1>();
        } else {
            cp_wait<0>();
        }
        __syncthreads();

        const uint32_t sb = smem_u + stg * XQ_STAGE;
        char* const sp = smem + stg * XQ_STAGE;

        // ---- convert A fp32 -> swizzled bf16 hi/lo (8 floats per thread) ----
        {
            const int r = tid >> 2, ch = tid & 3;   // r 0..127
            const float4* src = reinterpret_cast<const float4*>(
                sp + AF32 + r * 128 + ch * 32);
            float4 v0 = src[0], v1 = src[1];
            const float vf[8] = { v0.x, v0.y, v0.z, v0.w,
                                  v1.x, v1.y, v1.z, v1.w };
            __nv_bfloat16 hh[8], ll[8];
#pragma unroll
            for (int e = 0; e < 8; ++e) {
                hh[e] = __float2bfloat16_rn(vf[e]);
                ll[e] = __float2bfloat16_rn(vf[e] - __bfloat162float(hh[e]));
            }
            const uint32_t sw = r * 64 + ((ch ^ ((r >> 1) & 3)) << 4);
            *reinterpret_cast<uint4*>(sp + AHI + sw) =
                *reinterpret_cast<const uint4*>(hh);
            *reinterpret_cast<uint4*>(sp + ALO + sw) =
                *reinterpret_cast<const uint4*>(ll);
        }
        __syncthreads();

        // ---- MMA: 2 ks steps, fragments hoisted, 3 terms from regs ----
#pragma unroll
        for (int ks = 0; ks < 32; ks += 16) {
            const int ko = (ks >> 3);
            uint32_t aH[2][4], aL[2][4], bH[8][2], bL[8][2];
#pragma unroll
            for (int mt = 0; mt < 2; ++mt) {
                const int R = wm + mt * 16 + laneA_r;
                const int kk = ko + laneA_k;
                const uint32_t sw = R * 64 + ((kk ^ ((R >> 1) & 3)) << 4);
                LDSM_X4(aH[mt][0], aH[mt][1], aH[mt][2], aH[mt][3],
                        sb + AHI + sw);
                LDSM_X4(aL[mt][0], aL[mt][1], aL[mt][2], aL[mt][3],
                        sb + ALO + sw);
            }
#pragma unroll
            for (int g = 0; g < 4; ++g) {
                const int R = wn + (2 * g + laneB_ns) * 8 + laneB_r;
                const int kk = ko + laneB_k;
                const uint32_t sw = R * 64 + ((kk ^ ((R >> 1) & 3)) << 4);
                LDSM_X4(bH[2 * g][0], bH[2 * g][1],
                        bH[2 * g + 1][0], bH[2 * g + 1][1], sb + BHI + sw);
                LDSM_X4(bL[2 * g][0], bL[2 * g][1],
                        bL[2 * g + 1][0], bL[2 * g + 1][1], sb + BLO + sw);
            }
#pragma unroll
            for (int mt = 0; mt < 2; ++mt)
#pragma unroll
                for (int nt = 0; nt < 8; ++nt)
                    MMA_BF16(acc[mt][nt], aH[mt], bH[nt]);
#pragma unroll
            for (int mt = 0; mt < 2; ++mt)
#pragma unroll
                for (int nt = 0; nt < 8; ++nt)
                    MMA_BF16(acc[mt][nt], aL[mt], bH[nt]);
#pragma unroll
            for (int mt = 0; mt < 2; ++mt)
#pragma unroll
                for (int nt = 0; nt < 8; ++nt)
                    MMA_BF16(acc[mt][nt], aH[mt], bL[nt]);
        }
        __syncthreads();
    }

    // Epilogue with reshape-scramble scale
    const int rbase = bm + wm + (lane >> 2);
    const int cb0 = wn + 2 * (lane & 3);
#pragma unroll
    for (int mt = 0; mt < 2; ++mt) {
        const int R0 = rbase + mt * 16;
        const int R1 = R0 + 8;
        const int t0 = R0 & (T - 1);
        const int t1 = R1 & (T - 1);
#pragma unroll
        for (int nt = 0; nt < 8; ++nt) {
            const int C = cb0 + nt * 8;
            float2 v01, v23;
            v01.x = acc[mt][nt][0] * g_S[(size_t)C * T + t0];
            v01.y = acc[mt][nt][1] * g_S[(size_t)(C + 1) * T + t0];
            v23.x = acc[mt][nt][2] * g_S[(size_t)C * T + t1];
            v23.y = acc[mt][nt][3] * g_S[(size_t)(C + 1) * T + t1];
            *reinterpret_cast<float2*>(&out[(size_t)R0 * D + C]) = v01;
            *reinterpret_cast<float2*>(&out[(size_t)R1 * D + C]) = v23;
        }
    }
}

// ---------------------------------------------------------------------------
extern "C" void kernel_launch(void* const* d_in, const int* in_sizes, int n_in,
                              void* d_out, int out_size) {
    const float* x  = (const float*)d_in[0];
    const float* Wq = (const float*)d_in[1];
    const float* Wk = (const float*)d_in[2];
    const float* Wv = (const float*)d_in[3];
    float* out = (float*)d_out;

    cudaFuncSetAttribute(yk_gemm,
                         cudaFuncAttributeMaxDynamicSharedMemorySize, SMEM_SMALL);
    cudaFuncSetAttribute(xq_gemm,
                         cudaFuncAttributeMaxDynamicSharedMemorySize, SMEM_BIG);

    // W+A: weight splits (x=0,1) + wv row-sums (x=2)
    prep_kernel<<<dim3(3, 8), 256>>>(Wq, Wk, Wv);
    // B: vsum fold + y hi/lo
    y_kernel<<<T, 256>>>(x);
    // C: c = y @ Wk via warp-MMA, 64x64 tiles (128 CTAs)
    yk_gemm<<<dim3(T / 64, D / 64), 256, SMEM_SMALL>>>();
    // D: blocked decay scan -> S
    scan_local_kernel<<<SCAN_P, 256>>>();
    scan_carry_kernel<<<1, 256>>>();
    scan_combine_kernel<<<SCAN_P, 256>>>();
    // E: out = S2 .* (x @ Wq), 512-thread CTAs, fused x-split
    xq_gemm<<<MBIG / 128, 512, SMEM_BIG>>>(x, out);
}